// round 15
// baseline (speedup 1.0000x reference)
#include <cuda_runtime.h>
#include <cuda_fp16.h>
#include <cstdint>

// LSTM discriminator: B=2048, T=512, H=128.
// 128 CTAs x 512 threads (16 warps); warp w owns j in [8w,8w+8) of each gate.
// R14 base + depth-2 pipelined ldmatrix stream: only 2 LDSM issued at step
// start (cold L1-queue flood 256->128 wavefronts), remaining 6 slipped one
// per MMA k-group, so the tensor pipe starts ~200 cyc earlier each step.

#define T_STEPS 512
#define HDIM    128
#define MB      16
#define HSTR    136   // padded stride in halves (272B): LDSM + STS conflict-free

__device__ __forceinline__ __half2 tanh2(__half2 x) {
    uint32_t xi = *reinterpret_cast<uint32_t*>(&x), yi;
    asm volatile("tanh.approx.f16x2 %0, %1;" : "=r"(yi) : "r"(xi));
    return *reinterpret_cast<__half2*>(&yi);
}

__device__ __forceinline__ void mma16816_f16(uint32_t d[2], const uint32_t a[4],
                                             const uint32_t b[2]) {
    asm volatile(
        "mma.sync.aligned.m16n8k16.row.col.f16.f16.f16.f16 "
        "{%0,%1}, {%2,%3,%4,%5}, {%6,%7}, {%0,%1};\n"
        : "+r"(d[0]), "+r"(d[1])
        : "r"(a[0]), "r"(a[1]), "r"(a[2]), "r"(a[3]), "r"(b[0]), "r"(b[1]));
}

__device__ __forceinline__ void ldsm_x4(uint32_t a[4], uint32_t saddr) {
    asm volatile(
        "ldmatrix.sync.aligned.m8n8.x4.shared.b16 {%0,%1,%2,%3}, [%4];"
        : "=r"(a[0]), "=r"(a[1]), "=r"(a[2]), "=r"(a[3])
        : "r"(saddr));
}

__global__ __launch_bounds__(512, 1)
void lstm_disc_kernel(
    const float* __restrict__ x,      // [B, T]
    const float* __restrict__ hx0,    // [B, H]
    const float* __restrict__ cx0,    // [B, H]
    const float* __restrict__ W_ih,   // [4H, 1]
    const float* __restrict__ W_hh,   // [4H, H]
    const float* __restrict__ b_ih,   // [4H]
    const float* __restrict__ b_hh,   // [4H]
    const float* __restrict__ W_mlp,  // [1, H]
    const float* __restrict__ b_mlp,  // [1]
    float* __restrict__ out)          // [B, 1]
{
    __shared__ float xs[MB][T_STEPS + 1];   // col T_STEPS = pad for last prefetch
    __shared__ __align__(16) __half hbuf[2][MB][HSTR];
    __shared__ __half2 wih2[4][64];   // W_ih pairs (pre-halved for i,f,o)
    __shared__ __half2 bb2[4][64];    // b_ih+b_hh pairs (pre-halved for i,f,o)

    const int tid  = threadIdx.x;
    const int w    = tid >> 5;
    const int l    = tid & 31;
    const int qr   = l >> 2;
    const int ql   = l & 3;
    const int brow = blockIdx.x * MB;

    // ---- one-time loads ----
    for (int i = tid; i < MB * T_STEPS; i += 512)
        xs[i / T_STEPS][i % T_STEPS] = x[(size_t)(brow + i / T_STEPS) * T_STEPS + (i % T_STEPS)];
    if (tid < MB) xs[tid][T_STEPS] = 0.f;
    for (int i = tid; i < 4 * 64; i += 512) {
        int g = i >> 6, p = i & 63, j = 2 * p;
        float sc = (g == 2) ? 1.0f : 0.5f;
        wih2[g][p] = __floats2half2_rn(sc * W_ih[g * HDIM + j], sc * W_ih[g * HDIM + j + 1]);
        bb2[g][p]  = __floats2half2_rn(sc * (b_ih[g * HDIM + j] + b_hh[g * HDIM + j]),
                                       sc * (b_ih[g * HDIM + j + 1] + b_hh[g * HDIM + j + 1]));
    }
    for (int i = tid; i < MB * HDIM; i += 512) {
        int r = i / HDIM, j = i % HDIM;
        hbuf[0][r][j] = __float2half(hx0[(size_t)(brow + r) * HDIM + j]);
    }

    // W_hh -> f16 B fragments (pre-halved for i,f,o)
    uint32_t Bf[4][8][2];
    #pragma unroll
    for (int g = 0; g < 4; ++g) {
        float sc = (g == 2) ? 1.0f : 0.5f;
        #pragma unroll
        for (int kk = 0; kk < 8; ++kk) {
            int n = g * HDIM + w * 8 + qr;
            int k = kk * 16 + 2 * ql;
            float2 v0 = *reinterpret_cast<const float2*>(&W_hh[(size_t)n * HDIM + k]);
            float2 v1 = *reinterpret_cast<const float2*>(&W_hh[(size_t)n * HDIM + k + 8]);
            __half2 h0 = __floats2half2_rn(sc * v0.x, sc * v0.y);
            __half2 h1 = __floats2half2_rn(sc * v1.x, sc * v1.y);
            Bf[g][kk][0] = *reinterpret_cast<uint32_t*>(&h0);
            Bf[g][kk][1] = *reinterpret_cast<uint32_t*>(&h1);
        }
    }

    const int jp = w * 4 + ql;
    __half2 wi2[4], bi2[4];
    __syncthreads();
    #pragma unroll
    for (int g = 0; g < 4; ++g) { wi2[g] = wih2[g][jp]; bi2[g] = bb2[g][jp]; }

    __half2 cst[2];
    #pragma unroll
    for (int rr = 0; rr < 2; ++rr) {
        int r = brow + qr + 8 * rr;
        int j = w * 8 + 2 * ql;
        cst[rr] = __floats2half2_rn(cx0[(size_t)r * HDIM + j],
                                    cx0[(size_t)r * HDIM + j + 1]);
    }

    const int lrow = l & 15;
    const int lkof = (l >> 4) * 8;
    const __half2 h05 = __float2half2_rn(0.5f);

    uint32_t abase[2];
    abase[0] = (uint32_t)__cvta_generic_to_shared(&hbuf[0][lrow][lkof]);
    abase[1] = (uint32_t)__cvta_generic_to_shared(&hbuf[1][lrow][lkof]);
    uint32_t* sts0[2];
    sts0[0] = reinterpret_cast<uint32_t*>(&hbuf[0][qr][w * 8 + 2 * ql]);
    sts0[1] = reinterpret_cast<uint32_t*>(&hbuf[1][qr][w * 8 + 2 * ql]);

    // pre for t=0
    __half2 pre[4][2];
    {
        __half2 x0 = __float2half2_rn(xs[qr][0]);
        __half2 x1 = __float2half2_rn(xs[qr + 8][0]);
        #pragma unroll
        for (int g = 0; g < 4; ++g) {
            pre[g][0] = __hfma2(x0, wi2[g], bi2[g]);
            pre[g][1] = __hfma2(x1, wi2[g], bi2[g]);
        }
    }
    __syncthreads();

    // ---- recurrence ----
    #pragma unroll 1
    for (int t = 0; t < T_STEPS; ++t) {
        const int rb = t & 1, wbuf = rb ^ 1;
        const uint32_t ab = abase[rb];

        uint32_t acc[4][2];
        #pragma unroll
        for (int g = 0; g < 4; ++g) {
            acc[g][0] = *reinterpret_cast<uint32_t*>(&pre[g][0]);
            acc[g][1] = *reinterpret_cast<uint32_t*>(&pre[g][1]);
        }

        // depth-2 pipelined LDSM: buffers A[0..3] reused cyclically
        uint32_t A[4][4];
        ldsm_x4(A[0], ab + 0 * 32);              // kk0
        ldsm_x4(A[1], ab + 1 * 32);              // kk1
        // kk0
        #pragma unroll
        for (int g = 0; g < 4; ++g) mma16816_f16(acc[g], A[0], Bf[g][0]);
        ldsm_x4(A[2], ab + 2 * 32);              // kk2
        // kk1
        #pragma unroll
        for (int g = 0; g < 4; ++g) mma16816_f16(acc[g], A[1], Bf[g][1]);
        ldsm_x4(A[3], ab + 3 * 32);              // kk3
        // kk2
        #pragma unroll
        for (int g = 0; g < 4; ++g) mma16816_f16(acc[g], A[2], Bf[g][2]);
        ldsm_x4(A[0], ab + 4 * 32);              // kk4
        // kk3
        #pragma unroll
        for (int g = 0; g < 4; ++g) mma16816_f16(acc[g], A[3], Bf[g][3]);
        ldsm_x4(A[1], ab + 5 * 32);              // kk5
        ldsm_x4(A[2], ab + 6 * 32);              // kk6

        // ---- second k-half: gate-major i, g, f, o with pinned epilogue ----
        // gate i  (kk4..7 = A[0..3])
        mma16816_f16(acc[0], A[0], Bf[0][4]);
        ldsm_x4(A[3], ab + 7 * 32);              // kk7
        mma16816_f16(acc[0], A[1], Bf[0][5]);
        mma16816_f16(acc[0], A[2], Bf[0][6]);
        mma16816_f16(acc[0], A[3], Bf[0][7]);
        // gate g
        #pragma unroll
        for (int kk = 0; kk < 4; ++kk)
            mma16816_f16(acc[2], A[kk], Bf[2][kk + 4]);
        __half2 ti[2];
        #pragma unroll
        for (int rr = 0; rr < 2; ++rr)
            ti[rr] = tanh2(*reinterpret_cast<__half2*>(&acc[0][rr]));
        // gate f
        #pragma unroll
        for (int kk = 0; kk < 4; ++kk)
            mma16816_f16(acc[1], A[kk], Bf[1][kk + 4]);
        __half2 ig[2];
        #pragma unroll
        for (int rr = 0; rr < 2; ++rr) {
            __half2 gv = tanh2(*reinterpret_cast<__half2*>(&acc[2][rr]));
            __half2 iv = __hfma2(ti[rr], h05, h05);
            ig[rr] = __hmul2(iv, gv);
        }
        // gate o
        #pragma unroll
        for (int kk = 0; kk < 4; ++kk)
            mma16816_f16(acc[3], A[kk], Bf[3][kk + 4]);
        __half2 tc[2];
        #pragma unroll
        for (int rr = 0; rr < 2; ++rr) {
            __half2 tf = tanh2(*reinterpret_cast<__half2*>(&acc[1][rr]));
            __half2 fv = __hfma2(tf, h05, h05);
            __half2 c  = __hfma2(fv, cst[rr], ig[rr]);
            cst[rr] = c;
            tc[rr] = tanh2(c);
        }

        // pre(t+1) prefetch (fma pipe, fills drain window)
        {
            __half2 x0 = __float2half2_rn(xs[qr][t + 1]);
            __half2 x1 = __float2half2_rn(xs[qr + 8][t + 1]);
            #pragma unroll
            for (int g = 0; g < 4; ++g) {
                pre[g][0] = __hfma2(x0, wi2[g], bi2[g]);
                pre[g][1] = __hfma2(x1, wi2[g], bi2[g]);
            }
        }

        // tail: o-dependent ops only
        #pragma unroll
        for (int rr = 0; rr < 2; ++rr) {
            __half2 to = tanh2(*reinterpret_cast<__half2*>(&acc[3][rr]));
            __half2 ov = __hfma2(to, h05, h05);
            __half2 hv = __hmul2(ov, tc[rr]);
            sts0[wbuf][rr * 8 * HSTR / 2] = *reinterpret_cast<uint32_t*>(&hv);
        }
        __syncthreads();
    }

    // ---- final MLP + sigmoid ----  (h(T) in hbuf[0], T even)
    if (tid < 128) {
        int r = tid >> 3, q = tid & 7;
        float s = 0.f;
        #pragma unroll
        for (int k = 0; k < 16; ++k) {
            int j = q * 16 + k;
            s = fmaf(__half2float(hbuf[0][r][j]), W_mlp[j], s);
        }
        s += __shfl_xor_sync(0xffffffffu, s, 1);
        s += __shfl_xor_sync(0xffffffffu, s, 2);
        s += __shfl_xor_sync(0xffffffffu, s, 4);
        if (q == 0) {
            float z = s + b_mlp[0];
            out[brow + r] = 1.f / (1.f + __expf(-z));
        }
    }
}

extern "C" void kernel_launch(void* const* d_in, const int* in_sizes, int n_in,
                              void* d_out, int out_size) {
    const float* x     = (const float*)d_in[0];
    const float* hx0   = (const float*)d_in[1];
    const float* cx0   = (const float*)d_in[2];
    const float* W_ih  = (const float*)d_in[3];
    const float* W_hh  = (const float*)d_in[4];
    const float* b_ih  = (const float*)d_in[5];
    const float* b_hh  = (const float*)d_in[6];
    const float* W_mlp = (const float*)d_in[7];
    const float* b_mlp = (const float*)d_in[8];
    float* out = (float*)d_out;

    const int B = out_size;          // 2048
    dim3 grid(B / MB), block(512);
    lstm_disc_kernel<<<grid, block>>>(x, hx0, cx0, W_ih, W_hh, b_ih, b_hh,
                                      W_mlp, b_mlp, out);
}

// round 17
// speedup vs baseline: 1.0014x; 1.0014x over previous
#include <cuda_runtime.h>
#include <cuda_fp16.h>
#include <cstdint>

// LSTM discriminator: B=2048, T=512, H=128.
// 128 CTAs x 512 threads (16 warps); warp w owns j in [8w,8w+8) of each gate.
// R14 base + depth-2 pipelined ldmatrix stream: only 2 LDSM issued at step
// start (cold L1-queue flood 256->128 wavefronts), remaining 6 slipped one
// per MMA k-group, so the tensor pipe starts ~200 cyc earlier each step.

#define T_STEPS 512
#define HDIM    128
#define MB      16
#define HSTR    136   // padded stride in halves (272B): LDSM + STS conflict-free

__device__ __forceinline__ __half2 tanh2(__half2 x) {
    uint32_t xi = *reinterpret_cast<uint32_t*>(&x), yi;
    asm volatile("tanh.approx.f16x2 %0, %1;" : "=r"(yi) : "r"(xi));
    return *reinterpret_cast<__half2*>(&yi);
}

__device__ __forceinline__ void mma16816_f16(uint32_t d[2], const uint32_t a[4],
                                             const uint32_t b[2]) {
    asm volatile(
        "mma.sync.aligned.m16n8k16.row.col.f16.f16.f16.f16 "
        "{%0,%1}, {%2,%3,%4,%5}, {%6,%7}, {%0,%1};\n"
        : "+r"(d[0]), "+r"(d[1])
        : "r"(a[0]), "r"(a[1]), "r"(a[2]), "r"(a[3]), "r"(b[0]), "r"(b[1]));
}

__device__ __forceinline__ void ldsm_x4(uint32_t a[4], uint32_t saddr) {
    asm volatile(
        "ldmatrix.sync.aligned.m8n8.x4.shared.b16 {%0,%1,%2,%3}, [%4];"
        : "=r"(a[0]), "=r"(a[1]), "=r"(a[2]), "=r"(a[3])
        : "r"(saddr));
}

__global__ __launch_bounds__(512, 1)
void lstm_disc_kernel(
    const float* __restrict__ x,      // [B, T]
    const float* __restrict__ hx0,    // [B, H]
    const float* __restrict__ cx0,    // [B, H]
    const float* __restrict__ W_ih,   // [4H, 1]
    const float* __restrict__ W_hh,   // [4H, H]
    const float* __restrict__ b_ih,   // [4H]
    const float* __restrict__ b_hh,   // [4H]
    const float* __restrict__ W_mlp,  // [1, H]
    const float* __restrict__ b_mlp,  // [1]
    float* __restrict__ out)          // [B, 1]
{
    __shared__ float xs[MB][T_STEPS + 1];   // col T_STEPS = pad for last prefetch
    __shared__ __align__(16) __half hbuf[2][MB][HSTR];
    __shared__ __half2 wih2[4][64];   // W_ih pairs (pre-halved for i,f,o)
    __shared__ __half2 bb2[4][64];    // b_ih+b_hh pairs (pre-halved for i,f,o)

    const int tid  = threadIdx.x;
    const int w    = tid >> 5;
    const int l    = tid & 31;
    const int qr   = l >> 2;
    const int ql   = l & 3;
    const int brow = blockIdx.x * MB;

    // ---- one-time loads ----
    for (int i = tid; i < MB * T_STEPS; i += 512)
        xs[i / T_STEPS][i % T_STEPS] = x[(size_t)(brow + i / T_STEPS) * T_STEPS + (i % T_STEPS)];
    if (tid < MB) xs[tid][T_STEPS] = 0.f;
    for (int i = tid; i < 4 * 64; i += 512) {
        int g = i >> 6, p = i & 63, j = 2 * p;
        float sc = (g == 2) ? 1.0f : 0.5f;
        wih2[g][p] = __floats2half2_rn(sc * W_ih[g * HDIM + j], sc * W_ih[g * HDIM + j + 1]);
        bb2[g][p]  = __floats2half2_rn(sc * (b_ih[g * HDIM + j] + b_hh[g * HDIM + j]),
                                       sc * (b_ih[g * HDIM + j + 1] + b_hh[g * HDIM + j + 1]));
    }
    for (int i = tid; i < MB * HDIM; i += 512) {
        int r = i / HDIM, j = i % HDIM;
        hbuf[0][r][j] = __float2half(hx0[(size_t)(brow + r) * HDIM + j]);
    }

    // W_hh -> f16 B fragments (pre-halved for i,f,o)
    uint32_t Bf[4][8][2];
    #pragma unroll
    for (int g = 0; g < 4; ++g) {
        float sc = (g == 2) ? 1.0f : 0.5f;
        #pragma unroll
        for (int kk = 0; kk < 8; ++kk) {
            int n = g * HDIM + w * 8 + qr;
            int k = kk * 16 + 2 * ql;
            float2 v0 = *reinterpret_cast<const float2*>(&W_hh[(size_t)n * HDIM + k]);
            float2 v1 = *reinterpret_cast<const float2*>(&W_hh[(size_t)n * HDIM + k + 8]);
            __half2 h0 = __floats2half2_rn(sc * v0.x, sc * v0.y);
            __half2 h1 = __floats2half2_rn(sc * v1.x, sc * v1.y);
            Bf[g][kk][0] = *reinterpret_cast<uint32_t*>(&h0);
            Bf[g][kk][1] = *reinterpret_cast<uint32_t*>(&h1);
        }
    }

    const int jp = w * 4 + ql;
    __half2 wi2[4], bi2[4];
    __syncthreads();
    #pragma unroll
    for (int g = 0; g < 4; ++g) { wi2[g] = wih2[g][jp]; bi2[g] = bb2[g][jp]; }

    __half2 cst[2];
    #pragma unroll
    for (int rr = 0; rr < 2; ++rr) {
        int r = brow + qr + 8 * rr;
        int j = w * 8 + 2 * ql;
        cst[rr] = __floats2half2_rn(cx0[(size_t)r * HDIM + j],
                                    cx0[(size_t)r * HDIM + j + 1]);
    }

    const int lrow = l & 15;
    const int lkof = (l >> 4) * 8;
    const __half2 h05 = __float2half2_rn(0.5f);

    uint32_t abase[2];
    abase[0] = (uint32_t)__cvta_generic_to_shared(&hbuf[0][lrow][lkof]);
    abase[1] = (uint32_t)__cvta_generic_to_shared(&hbuf[1][lrow][lkof]);
    uint32_t* sts0[2];
    sts0[0] = reinterpret_cast<uint32_t*>(&hbuf[0][qr][w * 8 + 2 * ql]);
    sts0[1] = reinterpret_cast<uint32_t*>(&hbuf[1][qr][w * 8 + 2 * ql]);

    // pre for t=0
    __half2 pre[4][2];
    {
        __half2 x0 = __float2half2_rn(xs[qr][0]);
        __half2 x1 = __float2half2_rn(xs[qr + 8][0]);
        #pragma unroll
        for (int g = 0; g < 4; ++g) {
            pre[g][0] = __hfma2(x0, wi2[g], bi2[g]);
            pre[g][1] = __hfma2(x1, wi2[g], bi2[g]);
        }
    }
    __syncthreads();

    // ---- recurrence ----
    #pragma unroll 1
    for (int t = 0; t < T_STEPS; ++t) {
        const int rb = t & 1, wbuf = rb ^ 1;
        const uint32_t ab = abase[rb];

        uint32_t acc[4][2];
        #pragma unroll
        for (int g = 0; g < 4; ++g) {
            acc[g][0] = *reinterpret_cast<uint32_t*>(&pre[g][0]);
            acc[g][1] = *reinterpret_cast<uint32_t*>(&pre[g][1]);
        }

        // depth-2 pipelined LDSM: buffers A[0..3] reused cyclically
        uint32_t A[4][4];
        ldsm_x4(A[0], ab + 0 * 32);              // kk0
        ldsm_x4(A[1], ab + 1 * 32);              // kk1
        // kk0
        #pragma unroll
        for (int g = 0; g < 4; ++g) mma16816_f16(acc[g], A[0], Bf[g][0]);
        ldsm_x4(A[2], ab + 2 * 32);              // kk2
        // kk1
        #pragma unroll
        for (int g = 0; g < 4; ++g) mma16816_f16(acc[g], A[1], Bf[g][1]);
        ldsm_x4(A[3], ab + 3 * 32);              // kk3
        // kk2
        #pragma unroll
        for (int g = 0; g < 4; ++g) mma16816_f16(acc[g], A[2], Bf[g][2]);
        ldsm_x4(A[0], ab + 4 * 32);              // kk4
        // kk3
        #pragma unroll
        for (int g = 0; g < 4; ++g) mma16816_f16(acc[g], A[3], Bf[g][3]);
        ldsm_x4(A[1], ab + 5 * 32);              // kk5
        ldsm_x4(A[2], ab + 6 * 32);              // kk6

        // ---- second k-half: gate-major i, g, f, o with pinned epilogue ----
        // gate i  (kk4..7 = A[0..3])
        mma16816_f16(acc[0], A[0], Bf[0][4]);
        ldsm_x4(A[3], ab + 7 * 32);              // kk7
        mma16816_f16(acc[0], A[1], Bf[0][5]);
        mma16816_f16(acc[0], A[2], Bf[0][6]);
        mma16816_f16(acc[0], A[3], Bf[0][7]);
        // gate g
        #pragma unroll
        for (int kk = 0; kk < 4; ++kk)
            mma16816_f16(acc[2], A[kk], Bf[2][kk + 4]);
        __half2 ti[2];
        #pragma unroll
        for (int rr = 0; rr < 2; ++rr)
            ti[rr] = tanh2(*reinterpret_cast<__half2*>(&acc[0][rr]));
        // gate f
        #pragma unroll
        for (int kk = 0; kk < 4; ++kk)
            mma16816_f16(acc[1], A[kk], Bf[1][kk + 4]);
        __half2 ig[2];
        #pragma unroll
        for (int rr = 0; rr < 2; ++rr) {
            __half2 gv = tanh2(*reinterpret_cast<__half2*>(&acc[2][rr]));
            __half2 iv = __hfma2(ti[rr], h05, h05);
            ig[rr] = __hmul2(iv, gv);
        }
        // gate o
        #pragma unroll
        for (int kk = 0; kk < 4; ++kk)
            mma16816_f16(acc[3], A[kk], Bf[3][kk + 4]);
        __half2 tc[2];
        #pragma unroll
        for (int rr = 0; rr < 2; ++rr) {
            __half2 tf = tanh2(*reinterpret_cast<__half2*>(&acc[1][rr]));
            __half2 fv = __hfma2(tf, h05, h05);
            __half2 c  = __hfma2(fv, cst[rr], ig[rr]);
            cst[rr] = c;
            tc[rr] = tanh2(c);
        }

        // pre(t+1) prefetch (fma pipe, fills drain window)
        {
            __half2 x0 = __float2half2_rn(xs[qr][t + 1]);
            __half2 x1 = __float2half2_rn(xs[qr + 8][t + 1]);
            #pragma unroll
            for (int g = 0; g < 4; ++g) {
                pre[g][0] = __hfma2(x0, wi2[g], bi2[g]);
                pre[g][1] = __hfma2(x1, wi2[g], bi2[g]);
            }
        }

        // tail: o-dependent ops only
        #pragma unroll
        for (int rr = 0; rr < 2; ++rr) {
            __half2 to = tanh2(*reinterpret_cast<__half2*>(&acc[3][rr]));
            __half2 ov = __hfma2(to, h05, h05);
            __half2 hv = __hmul2(ov, tc[rr]);
            sts0[wbuf][rr * 8 * HSTR / 2] = *reinterpret_cast<uint32_t*>(&hv);
        }
        __syncthreads();
    }

    // ---- final MLP + sigmoid ----  (h(T) in hbuf[0], T even)
    if (tid < 128) {
        int r = tid >> 3, q = tid & 7;
        float s = 0.f;
        #pragma unroll
        for (int k = 0; k < 16; ++k) {
            int j = q * 16 + k;
            s = fmaf(__half2float(hbuf[0][r][j]), W_mlp[j], s);
        }
        s += __shfl_xor_sync(0xffffffffu, s, 1);
        s += __shfl_xor_sync(0xffffffffu, s, 2);
        s += __shfl_xor_sync(0xffffffffu, s, 4);
        if (q == 0) {
            float z = s + b_mlp[0];
            out[brow + r] = 1.f / (1.f + __expf(-z));
        }
    }
}

extern "C" void kernel_launch(void* const* d_in, const int* in_sizes, int n_in,
                              void* d_out, int out_size) {
    const float* x     = (const float*)d_in[0];
    const float* hx0   = (const float*)d_in[1];
    const float* cx0   = (const float*)d_in[2];
    const float* W_ih  = (const float*)d_in[3];
    const float* W_hh  = (const float*)d_in[4];
    const float* b_ih  = (const float*)d_in[5];
    const float* b_hh  = (const float*)d_in[6];
    const float* W_mlp = (const float*)d_in[7];
    const float* b_mlp = (const float*)d_in[8];
    float* out = (float*)d_out;

    const int B = out_size;          // 2048
    dim3 grid(B / MB), block(512);
    lstm_disc_kernel<<<grid, block>>>(x, hx0, cx0, W_ih, W_hh, b_ih, b_hh,
                                      W_mlp, b_mlp, out);
}